// round 1
// baseline (speedup 1.0000x reference)
#include <cuda_runtime.h>
#include <cuda_bf16.h>

// auxiliary_loss: flattened ranking loss over y_pred (f32) and labels (i32 in {0,1}).
// loss = 0.2 * (pos*sum_neg - neg*sum_pos) / (pos*neg), with sum_neg = sum_all - sum_pos.
// Pure memory-bound triple reduction: sum(y), sum(y*lab), sum(lab).

#define DETA 0.2

constexpr int RED_BLOCKS  = 1184;   // 148 SMs * 8 CTAs
constexpr int RED_THREADS = 256;

// Per-block partials (scratch: __device__ globals, no allocation).
__device__ float g_psum_all[RED_BLOCKS];
__device__ float g_psum_pos[RED_BLOCKS];
__device__ int   g_pcnt[RED_BLOCKS];

__device__ __forceinline__ float warp_red_f(float v) {
    #pragma unroll
    for (int o = 16; o > 0; o >>= 1) v += __shfl_down_sync(0xffffffffu, v, o);
    return v;
}
__device__ __forceinline__ int warp_red_i(int v) {
    #pragma unroll
    for (int o = 16; o > 0; o >>= 1) v += __shfl_down_sync(0xffffffffu, v, o);
    return v;
}

__global__ __launch_bounds__(RED_THREADS)
void partial_reduce_kernel(const float4* __restrict__ y4,
                           const int4*   __restrict__ l4,
                           long long nvec,
                           const float* __restrict__ ytail,
                           const int*   __restrict__ ltail,
                           int tail)
{
    float sa = 0.0f, sp = 0.0f;
    int   c  = 0;

    long long stride = (long long)gridDim.x * blockDim.x;
    for (long long i = (long long)blockIdx.x * blockDim.x + threadIdx.x;
         i < nvec; i += stride) {
        float4 v = y4[i];
        int4   l = l4[i];
        sa += (v.x + v.y) + (v.z + v.w);
        float p = 0.0f;
        if (l.x) p += v.x;
        if (l.y) p += v.y;
        if (l.z) p += v.z;
        if (l.w) p += v.w;
        sp += p;
        c  += l.x + l.y + l.z + l.w;
    }

    // Scalar tail (n % 4), handled once by block 0.
    if (blockIdx.x == 0 && (int)threadIdx.x < tail) {
        float v = ytail[threadIdx.x];
        int   l = ltail[threadIdx.x];
        sa += v;
        if (l) { sp += v; c += 1; }
    }

    // Warp reduce
    sa = warp_red_f(sa);
    sp = warp_red_f(sp);
    c  = warp_red_i(c);

    __shared__ float s_sa[RED_THREADS / 32];
    __shared__ float s_sp[RED_THREADS / 32];
    __shared__ int   s_c [RED_THREADS / 32];
    int wid = threadIdx.x >> 5;
    int lid = threadIdx.x & 31;
    if (lid == 0) { s_sa[wid] = sa; s_sp[wid] = sp; s_c[wid] = c; }
    __syncthreads();

    if (wid == 0) {
        constexpr int NW = RED_THREADS / 32;
        float a = (lid < NW) ? s_sa[lid] : 0.0f;
        float p = (lid < NW) ? s_sp[lid] : 0.0f;
        int   k = (lid < NW) ? s_c [lid] : 0;
        a = warp_red_f(a);
        p = warp_red_f(p);
        k = warp_red_i(k);
        if (lid == 0) {
            g_psum_all[blockIdx.x] = a;
            g_psum_pos[blockIdx.x] = p;
            g_pcnt[blockIdx.x]     = k;
        }
    }
}

__device__ __forceinline__ double warp_red_d(double v) {
    #pragma unroll
    for (int o = 16; o > 0; o >>= 1) v += __shfl_down_sync(0xffffffffu, v, o);
    return v;
}

__global__ __launch_bounds__(256)
void finalize_kernel(float* __restrict__ out, double n_total)
{
    double sa = 0.0, sp = 0.0;
    long long c = 0;
    for (int i = threadIdx.x; i < RED_BLOCKS; i += blockDim.x) {
        sa += (double)g_psum_all[i];
        sp += (double)g_psum_pos[i];
        c  += (long long)g_pcnt[i];
    }
    sa = warp_red_d(sa);
    sp = warp_red_d(sp);
    long long cl = c;
    #pragma unroll
    for (int o = 16; o > 0; o >>= 1) cl += __shfl_down_sync(0xffffffffu, cl, o);

    __shared__ double d_sa[8], d_sp[8];
    __shared__ long long d_c[8];
    int wid = threadIdx.x >> 5;
    int lid = threadIdx.x & 31;
    if (lid == 0) { d_sa[wid] = sa; d_sp[wid] = sp; d_c[wid] = cl; }
    __syncthreads();

    if (threadIdx.x == 0) {
        double SA = 0.0, SP = 0.0;
        long long C = 0;
        #pragma unroll
        for (int i = 0; i < 8; i++) { SA += d_sa[i]; SP += d_sp[i]; C += d_c[i]; }

        double pos = (double)C;
        double neg = n_total - pos;
        bool valid = (pos > 0.0) && (neg > 0.0);
        double sum_neg = SA - SP;
        double denom = valid ? pos * neg : 1.0;
        double loss = DETA * (pos * sum_neg - neg * SP) / denom;
        out[0] = valid ? (float)loss : 0.0f;
    }
}

extern "C" void kernel_launch(void* const* d_in, const int* in_sizes, int n_in,
                              void* d_out, int out_size)
{
    const float* y   = (const float*)d_in[0];
    const int*   lab = (const int*)d_in[1];
    int n = in_sizes[0];

    long long nvec = (long long)(n >> 2);
    int tail = n & 3;
    const float* ytail = y + (nvec << 2);
    const int*   ltail = lab + (nvec << 2);

    partial_reduce_kernel<<<RED_BLOCKS, RED_THREADS>>>(
        (const float4*)y, (const int4*)lab, nvec, ytail, ltail, tail);
    finalize_kernel<<<1, 256>>>((float*)d_out, (double)n);
}